// round 7
// baseline (speedup 1.0000x reference)
#include <cuda_runtime.h>
#include <math.h>

// Problem constants
#define BATCH 128
#define HDIM  512
#define IDIM  512
#define NG    (6 * HDIM)   // 3072 gate columns
#define INV_SQRT_H 0.04419417382415922f  // 1/sqrt(512)

// Output layout: concat(h_t [B,H], C_t [B,H,H], m_t [B,H], n_t [B,H])
#define OUT_H 0
#define OUT_C (BATCH * HDIM)                                // 65536
#define OUT_M (OUT_C + (long)BATCH * HDIM * HDIM)           // 33619968
#define OUT_N (OUT_M + BATCH * HDIM)                        // 33685504

// Scratch (device globals — no allocation allowed)
__device__ float g_part[2][BATCH * NG];  // split-K partial gate sums
__device__ float g_q[BATCH * HDIM];      // biased q (for stream kernel)
__device__ float g_f[BATCH * HDIM];
__device__ float g_add[BATCH * HDIM];
__device__ float g_o[BATCH * HDIM];
__device__ float g_sumq[BATCH];
__device__ float g_invden[BATCH];

// ---------------------------------------------------------------------------
// K1: partial gates = x @ W^T, split-K=2, fp32 FFMA.
// 4x8 register tile (32 FMA per 12 smem-floats -> 1.5 B/FMA-lane, below the
// 128B/cyc smem crossbar bind that limited the 2x4 version at L1=69%).
// BM=32, BN=64, BK=16, 64 threads. grid (48,4,2)=384 blocks, 2.6 blocks/SM.
// ---------------------------------------------------------------------------
#define SBM 32
#define SBN 64
#define SBK 16
#define KSPLIT 256   // IDIM / 2
#define SAPAD 36     // 144B row stride: multiple of 16B, float4-aligned
#define SBPAD 68     // 272B row stride: multiple of 16B

__global__ __launch_bounds__(64) void gemm_splitk_kernel(
    const float* __restrict__ x,    // [128,512]
    const float* __restrict__ Wm)   // [3072,512]
{
    __shared__ float sA[SBK][SAPAD];
    __shared__ float sB[SBK][SBPAD];

    int tid = threadIdx.x;          // 0..63
    int n0 = blockIdx.x * SBN;
    int m0 = blockIdx.y * SBM;
    int kbase = blockIdx.z * KSPLIT;
    float* dst = &g_part[blockIdx.z][0];

    int tx = tid & 7;               // 8 col-groups * 8 = 64 cols
    int ty = tid >> 3;              // 8 row-groups * 4 = 32 rows

    // A loader: thread -> row (tid>>1), k-quad (tid&1)*8 ; 2 float4 each
    int arow = tid >> 1;
    int akq  = (tid & 1) * 8;
    // B loader: thread -> row tid ; 4 float4 (full 16-float row chunk)
    const float* Aptr = x  + (long)(m0 + arow) * IDIM + kbase + akq;
    const float* Bptr = Wm + (long)(n0 + tid) * IDIM + kbase;

    float acc[4][8];
#pragma unroll
    for (int i = 0; i < 4; i++)
#pragma unroll
        for (int j = 0; j < 8; j++) acc[i][j] = 0.f;

    // prefetch first tile into registers
    float4 pa0 = *reinterpret_cast<const float4*>(Aptr);
    float4 pa1 = *reinterpret_cast<const float4*>(Aptr + 4);
    float4 pb0 = *reinterpret_cast<const float4*>(Bptr);
    float4 pb1 = *reinterpret_cast<const float4*>(Bptr + 4);
    float4 pb2 = *reinterpret_cast<const float4*>(Bptr + 8);
    float4 pb3 = *reinterpret_cast<const float4*>(Bptr + 12);

    for (int kt = 0; kt < KSPLIT; kt += SBK) {
        // scatter prefetched tile into smem (k-major)
        sA[akq + 0][arow] = pa0.x; sA[akq + 1][arow] = pa0.y;
        sA[akq + 2][arow] = pa0.z; sA[akq + 3][arow] = pa0.w;
        sA[akq + 4][arow] = pa1.x; sA[akq + 5][arow] = pa1.y;
        sA[akq + 6][arow] = pa1.z; sA[akq + 7][arow] = pa1.w;
        sB[ 0][tid] = pb0.x; sB[ 1][tid] = pb0.y; sB[ 2][tid] = pb0.z; sB[ 3][tid] = pb0.w;
        sB[ 4][tid] = pb1.x; sB[ 5][tid] = pb1.y; sB[ 6][tid] = pb1.z; sB[ 7][tid] = pb1.w;
        sB[ 8][tid] = pb2.x; sB[ 9][tid] = pb2.y; sB[10][tid] = pb2.z; sB[11][tid] = pb2.w;
        sB[12][tid] = pb3.x; sB[13][tid] = pb3.y; sB[14][tid] = pb3.z; sB[15][tid] = pb3.w;
        __syncthreads();

        if (kt + SBK < KSPLIT) {   // prefetch next tile during compute
            pa0 = *reinterpret_cast<const float4*>(Aptr + kt + SBK);
            pa1 = *reinterpret_cast<const float4*>(Aptr + kt + SBK + 4);
            pb0 = *reinterpret_cast<const float4*>(Bptr + kt + SBK);
            pb1 = *reinterpret_cast<const float4*>(Bptr + kt + SBK + 4);
            pb2 = *reinterpret_cast<const float4*>(Bptr + kt + SBK + 8);
            pb3 = *reinterpret_cast<const float4*>(Bptr + kt + SBK + 12);
        }

#pragma unroll
        for (int k = 0; k < SBK; k++) {
            float4 a  = *reinterpret_cast<const float4*>(&sA[k][ty * 4]);
            float4 b0 = *reinterpret_cast<const float4*>(&sB[k][tx * 8]);
            float4 b1 = *reinterpret_cast<const float4*>(&sB[k][tx * 8 + 4]);
            float av[4] = {a.x, a.y, a.z, a.w};
            float bv[8] = {b0.x, b0.y, b0.z, b0.w, b1.x, b1.y, b1.z, b1.w};
#pragma unroll
            for (int i = 0; i < 4; i++)
#pragma unroll
                for (int j = 0; j < 8; j++) acc[i][j] += av[i] * bv[j];
        }
        __syncthreads();
    }

#pragma unroll
    for (int i = 0; i < 4; i++) {
        int m = m0 + ty * 4 + i;
        float4 o0 = make_float4(acc[i][0], acc[i][1], acc[i][2], acc[i][3]);
        float4 o1 = make_float4(acc[i][4], acc[i][5], acc[i][6], acc[i][7]);
        *reinterpret_cast<float4*>(dst + (long)m * NG + n0 + tx * 8)     = o0;
        *reinterpret_cast<float4*>(dst + (long)m * NG + n0 + tx * 8 + 4) = o1;
    }
}

// ---------------------------------------------------------------------------
// K2: fused partial-sum + bias + gate elementwise + per-batch reductions.
// One block (512 thr) per batch.
// ---------------------------------------------------------------------------
__global__ __launch_bounds__(512) void gatered_kernel(
    const float* __restrict__ m_prev,
    const float* __restrict__ n_prev,
    const float* __restrict__ bias,
    float* __restrict__ out)
{
    int b = blockIdx.x;
    int h = threadIdx.x;           // 0..511
    int idx = b * HDIM + h;
    const float* p0 = &g_part[0][(long)b * NG];
    const float* p1 = &g_part[1][(long)b * NG];

    float ig = (p0[h]            + p1[h])            + bias[h];
    float fg = (p0[HDIM + h]     + p1[HDIM + h])     + bias[HDIM + h];
    float og = (p0[2 * HDIM + h] + p1[2 * HDIM + h]) + bias[2 * HDIM + h];
    float qv = (p0[3 * HDIM + h] + p1[3 * HDIM + h]) + bias[3 * HDIM + h];
    float kg = (p0[4 * HDIM + h] + p1[4 * HDIM + h]) + bias[4 * HDIM + h];
    float vg = (p0[5 * HDIM + h] + p1[5 * HDIM + h]) + bias[5 * HDIM + h];

    float mp = m_prev[idx];
    float mt = fmaxf(fg + mp, ig);
    float it = expf(ig - mt);
    float ft = expf(fg + mp - mt);
    float kt = INV_SQRT_H * kg;
    float nt = ft * n_prev[idx] + it * kt;

    out[OUT_M + idx] = mt;
    out[OUT_N + idx] = nt;
    g_q[idx]   = qv;
    g_f[idx]   = ft;
    g_add[idx] = it * vg * kt;
    g_o[idx]   = 1.f / (1.f + expf(-og));

    // block reductions: sq = sum(q), nq = dot(n_t, q)
    float sq = qv;
    float nq = nt * qv;
    for (int s = 16; s; s >>= 1) {
        sq += __shfl_xor_sync(0xffffffffu, sq, s);
        nq += __shfl_xor_sync(0xffffffffu, nq, s);
    }
    __shared__ float s1[16], s2[16];
    int warp = h >> 5, lane = h & 31;
    if (lane == 0) { s1[warp] = sq; s2[warp] = nq; }
    __syncthreads();
    if (warp == 0) {
        sq = (lane < 16) ? s1[lane] : 0.f;
        nq = (lane < 16) ? s2[lane] : 0.f;
        for (int s = 8; s; s >>= 1) {
            sq += __shfl_xor_sync(0xffffffffu, sq, s);
            nq += __shfl_xor_sync(0xffffffffu, nq, s);
        }
        if (lane == 0) {
            g_sumq[b]   = sq;
            g_invden[b] = 1.f / fmaxf(fabsf(nq), 1e-6f);
        }
    }
}

// ---------------------------------------------------------------------------
// K3: THE bandwidth kernel. One warp per C row (2KB): C_t = f*C_prev + add,
// fused Cq = f*dot(C_prev_row, q) + add*sum_q, and h_t written directly.
// ---------------------------------------------------------------------------
__global__ __launch_bounds__(256) void stream_C_kernel(
    const float* __restrict__ Cprev,
    float* __restrict__ out)
{
    __shared__ float sq[HDIM];
    int b  = blockIdx.x >> 6;     // 64 blocks per batch (512 rows / 8)
    int rg = blockIdx.x & 63;
    int tid = threadIdx.x;

    // load biased q[b,:] into smem (float2 x 256 threads)
    const float* qrow = g_q + (long)b * HDIM;
    reinterpret_cast<float2*>(sq)[tid] = reinterpret_cast<const float2*>(qrow)[tid];
    __syncthreads();

    int warp = tid >> 5, lane = tid & 31;
    int i = rg * 8 + warp;
    int bh = b * HDIM + i;
    long rowoff = ((long)b * HDIM + i) * HDIM;

    float fv = g_f[bh];
    float av = g_add[bh];

    const float4* src = reinterpret_cast<const float4*>(Cprev + rowoff);
    float4*       dst = reinterpret_cast<float4*>(out + OUT_C + rowoff);
    const float4* qsv = reinterpret_cast<const float4*>(sq);

    // batch the 4 independent 16B loads first (MLP), then compute+store
    float4 c[4], qv[4];
#pragma unroll
    for (int u = 0; u < 4; u++) c[u] = __ldcs(&src[lane + u * 32]);
#pragma unroll
    for (int u = 0; u < 4; u++) qv[u] = qsv[lane + u * 32];

    float dot = 0.f;
#pragma unroll
    for (int u = 0; u < 4; u++) {
        dot += c[u].x * qv[u].x + c[u].y * qv[u].y
             + c[u].z * qv[u].z + c[u].w * qv[u].w;
        float4 o;
        o.x = fv * c[u].x + av;
        o.y = fv * c[u].y + av;
        o.z = fv * c[u].z + av;
        o.w = fv * c[u].w + av;
        __stcs(&dst[lane + u * 32], o);
    }
    for (int s = 16; s; s >>= 1) dot += __shfl_xor_sync(0xffffffffu, dot, s);
    if (lane == 0) {
        float cq = fv * dot + av * g_sumq[b];
        out[OUT_H + bh] = g_o[bh] * cq * g_invden[b];
    }
}

// ---------------------------------------------------------------------------
// Launch. Inputs (metadata order): x, h_prev, C_prev, m_prev, n_prev, W, b
// ---------------------------------------------------------------------------
extern "C" void kernel_launch(void* const* d_in, const int* in_sizes, int n_in,
                              void* d_out, int out_size)
{
    const float* x      = (const float*)d_in[0];
    // d_in[1] = h_prev (unused by reference)
    const float* C_prev = (const float*)d_in[2];
    const float* m_prev = (const float*)d_in[3];
    const float* n_prev = (const float*)d_in[4];
    const float* W      = (const float*)d_in[5];
    const float* bias   = (const float*)d_in[6];
    float* out = (float*)d_out;

    // K1: split-K fp32 GEMM, 4x8 reg tile (384 blocks x 64 threads)
    dim3 ggrid(NG / SBN, BATCH / SBM, 2);
    gemm_splitk_kernel<<<ggrid, 64>>>(x, W);

    // K2: fused split-K sum + bias + gate elementwise + reductions
    gatered_kernel<<<BATCH, 512>>>(m_prev, n_prev, bias, out);

    // K3: C stream + fused Cq + h_t
    stream_C_kernel<<<BATCH * (HDIM / 8), 256>>>(C_prev, out);
}

// round 8
// speedup vs baseline: 1.1228x; 1.1228x over previous
#include <cuda_runtime.h>
#include <math.h>

// Problem constants
#define BATCH 128
#define HDIM  512
#define IDIM  512
#define NG    (6 * HDIM)   // 3072 gate columns
#define INV_SQRT_H 0.04419417382415922f  // 1/sqrt(512)

// Output layout: concat(h_t [B,H], C_t [B,H,H], m_t [B,H], n_t [B,H])
#define OUT_H 0
#define OUT_C (BATCH * HDIM)                                // 65536
#define OUT_M (OUT_C + (long)BATCH * HDIM * HDIM)           // 33619968
#define OUT_N (OUT_M + BATCH * HDIM)                        // 33685504

// Scratch (device globals — no allocation allowed)
__device__ float g_part[2][BATCH * NG];  // split-K partial gate sums
__device__ float g_q[BATCH * HDIM];      // biased q (for stream kernel)
__device__ float g_f[BATCH * HDIM];
__device__ float g_add[BATCH * HDIM];
__device__ float g_o[BATCH * HDIM];
__device__ float g_sumq[BATCH];
__device__ float g_invden[BATCH];

// ---------------------------------------------------------------------------
// K1: partial gates = x @ W^T, split-K=2, fp32 FFMA.
// 4x4 register tile, 128 threads (thread grid 8x16), BM=32, BN=64, BK=16.
// grid (48,4,2) = 384 blocks x 4 warps = 10.4 warps/SM AND 2 B/FMA-lane smem
// traffic — balances the crossbar bind (R6: 2x4@69% L1) against the latency
// bind (R7: 4x8 @ 5 warps/SM).
// ---------------------------------------------------------------------------
#define SBM 32
#define SBN 64
#define SBK 16
#define KSPLIT 256   // IDIM / 2
#define SAPAD 36     // 144B row stride (16B multiple -> float4 aligned)
#define SBPAD 68     // 272B row stride

__global__ __launch_bounds__(128) void gemm_splitk_kernel(
    const float* __restrict__ x,    // [128,512]
    const float* __restrict__ Wm)   // [3072,512]
{
    __shared__ float sA[SBK][SAPAD];
    __shared__ float sB[SBK][SBPAD];

    int tid = threadIdx.x;          // 0..127
    int n0 = blockIdx.x * SBN;
    int m0 = blockIdx.y * SBM;
    int kbase = blockIdx.z * KSPLIT;
    float* dst = &g_part[blockIdx.z][0];

    int tx = tid & 15;              // 16 col-groups * 4 = 64 cols
    int ty = tid >> 4;              // 8  row-groups * 4 = 32 rows

    // A loader: 32 rows x 16 k = 128 float4 -> 1 per thread
    int arow = tid >> 2, akq = (tid & 3) * 4;
    // B loader: 64 rows x 16 k = 256 float4 -> 2 per thread
    int brow = tid >> 1, bkq = (tid & 1) * 8;

    const float* Aptr = x  + (long)(m0 + arow) * IDIM + kbase + akq;
    const float* Bptr = Wm + (long)(n0 + brow) * IDIM + kbase + bkq;

    float acc[4][4];
#pragma unroll
    for (int i = 0; i < 4; i++)
#pragma unroll
        for (int j = 0; j < 4; j++) acc[i][j] = 0.f;

    // register prefetch of first tile
    float4 pa  = *reinterpret_cast<const float4*>(Aptr);
    float4 pb0 = *reinterpret_cast<const float4*>(Bptr);
    float4 pb1 = *reinterpret_cast<const float4*>(Bptr + 4);

    for (int kt = 0; kt < KSPLIT; kt += SBK) {
        sA[akq + 0][arow] = pa.x;  sA[akq + 1][arow] = pa.y;
        sA[akq + 2][arow] = pa.z;  sA[akq + 3][arow] = pa.w;
        sB[bkq + 0][brow] = pb0.x; sB[bkq + 1][brow] = pb0.y;
        sB[bkq + 2][brow] = pb0.z; sB[bkq + 3][brow] = pb0.w;
        sB[bkq + 4][brow] = pb1.x; sB[bkq + 5][brow] = pb1.y;
        sB[bkq + 6][brow] = pb1.z; sB[bkq + 7][brow] = pb1.w;
        __syncthreads();

        if (kt + SBK < KSPLIT) {   // prefetch next tile during compute
            pa  = *reinterpret_cast<const float4*>(Aptr + kt + SBK);
            pb0 = *reinterpret_cast<const float4*>(Bptr + kt + SBK);
            pb1 = *reinterpret_cast<const float4*>(Bptr + kt + SBK + 4);
        }

#pragma unroll
        for (int k = 0; k < SBK; k++) {
            float4 a = *reinterpret_cast<const float4*>(&sA[k][ty * 4]);
            float4 b = *reinterpret_cast<const float4*>(&sB[k][tx * 4]);
            float av[4] = {a.x, a.y, a.z, a.w};
            float bv[4] = {b.x, b.y, b.z, b.w};
#pragma unroll
            for (int i = 0; i < 4; i++)
#pragma unroll
                for (int j = 0; j < 4; j++) acc[i][j] += av[i] * bv[j];
        }
        __syncthreads();
    }

#pragma unroll
    for (int i = 0; i < 4; i++) {
        int m = m0 + ty * 4 + i;
        float4 o = make_float4(acc[i][0], acc[i][1], acc[i][2], acc[i][3]);
        *reinterpret_cast<float4*>(dst + (long)m * NG + n0 + tx * 4) = o;
    }
}

// ---------------------------------------------------------------------------
// K2: fused partial-sum + bias + gate elementwise + per-batch reductions.
// One block (512 thr) per batch.
// ---------------------------------------------------------------------------
__global__ __launch_bounds__(512) void gatered_kernel(
    const float* __restrict__ m_prev,
    const float* __restrict__ n_prev,
    const float* __restrict__ bias,
    float* __restrict__ out)
{
    int b = blockIdx.x;
    int h = threadIdx.x;           // 0..511
    int idx = b * HDIM + h;
    const float* p0 = &g_part[0][(long)b * NG];
    const float* p1 = &g_part[1][(long)b * NG];

    float ig = (p0[h]            + p1[h])            + bias[h];
    float fg = (p0[HDIM + h]     + p1[HDIM + h])     + bias[HDIM + h];
    float og = (p0[2 * HDIM + h] + p1[2 * HDIM + h]) + bias[2 * HDIM + h];
    float qv = (p0[3 * HDIM + h] + p1[3 * HDIM + h]) + bias[3 * HDIM + h];
    float kg = (p0[4 * HDIM + h] + p1[4 * HDIM + h]) + bias[4 * HDIM + h];
    float vg = (p0[5 * HDIM + h] + p1[5 * HDIM + h]) + bias[5 * HDIM + h];

    float mp = m_prev[idx];
    float mt = fmaxf(fg + mp, ig);
    float it = expf(ig - mt);
    float ft = expf(fg + mp - mt);
    float kt = INV_SQRT_H * kg;
    float nt = ft * n_prev[idx] + it * kt;

    out[OUT_M + idx] = mt;
    out[OUT_N + idx] = nt;
    g_q[idx]   = qv;
    g_f[idx]   = ft;
    g_add[idx] = it * vg * kt;
    g_o[idx]   = 1.f / (1.f + expf(-og));

    // block reductions: sq = sum(q), nq = dot(n_t, q)
    float sq = qv;
    float nq = nt * qv;
    for (int s = 16; s; s >>= 1) {
        sq += __shfl_xor_sync(0xffffffffu, sq, s);
        nq += __shfl_xor_sync(0xffffffffu, nq, s);
    }
    __shared__ float s1[16], s2[16];
    int warp = h >> 5, lane = h & 31;
    if (lane == 0) { s1[warp] = sq; s2[warp] = nq; }
    __syncthreads();
    if (warp == 0) {
        sq = (lane < 16) ? s1[lane] : 0.f;
        nq = (lane < 16) ? s2[lane] : 0.f;
        for (int s = 8; s; s >>= 1) {
            sq += __shfl_xor_sync(0xffffffffu, sq, s);
            nq += __shfl_xor_sync(0xffffffffu, nq, s);
        }
        if (lane == 0) {
            g_sumq[b]   = sq;
            g_invden[b] = 1.f / fmaxf(fabsf(nq), 1e-6f);
        }
    }
}

// ---------------------------------------------------------------------------
// K3: THE bandwidth kernel. TWO rows per warp (8 outstanding 16B loads ->
// deeper MLP than the 4 of the 1-row version). C_t = f*C_prev + add, fused
// Cq = f*dot(row,q) + add*sum_q, h_t written directly.
// ---------------------------------------------------------------------------
__global__ __launch_bounds__(256) void stream_C_kernel(
    const float* __restrict__ Cprev,
    float* __restrict__ out)
{
    __shared__ float sq[HDIM];
    int b  = blockIdx.x >> 5;     // 32 blocks per batch (512 rows / 16)
    int rg = blockIdx.x & 31;
    int tid = threadIdx.x;

    // load biased q[b,:] into smem (float2 x 256 threads)
    const float* qrow = g_q + (long)b * HDIM;
    reinterpret_cast<float2*>(sq)[tid] = reinterpret_cast<const float2*>(qrow)[tid];
    __syncthreads();

    int warp = tid >> 5, lane = tid & 31;
    int i0 = rg * 16 + warp * 2;              // this warp's two rows
    int bh0 = b * HDIM + i0;
    int bh1 = bh0 + 1;
    long ro0 = ((long)b * HDIM + i0) * HDIM;
    long ro1 = ro0 + HDIM;

    float fv0 = g_f[bh0], av0 = g_add[bh0];
    float fv1 = g_f[bh1], av1 = g_add[bh1];

    const float4* s0 = reinterpret_cast<const float4*>(Cprev + ro0);
    const float4* s1 = reinterpret_cast<const float4*>(Cprev + ro1);
    float4* d0 = reinterpret_cast<float4*>(out + OUT_C + ro0);
    float4* d1 = reinterpret_cast<float4*>(out + OUT_C + ro1);
    const float4* qsv = reinterpret_cast<const float4*>(sq);

    // batch 8 independent 16B loads (MLP=8)
    float4 c0[4], c1[4], qv[4];
#pragma unroll
    for (int u = 0; u < 4; u++) c0[u] = __ldcs(&s0[lane + u * 32]);
#pragma unroll
    for (int u = 0; u < 4; u++) c1[u] = __ldcs(&s1[lane + u * 32]);
#pragma unroll
    for (int u = 0; u < 4; u++) qv[u] = qsv[lane + u * 32];

    float dot0 = 0.f, dot1 = 0.f;
#pragma unroll
    for (int u = 0; u < 4; u++) {
        dot0 += c0[u].x * qv[u].x + c0[u].y * qv[u].y
              + c0[u].z * qv[u].z + c0[u].w * qv[u].w;
        float4 o;
        o.x = fv0 * c0[u].x + av0;
        o.y = fv0 * c0[u].y + av0;
        o.z = fv0 * c0[u].z + av0;
        o.w = fv0 * c0[u].w + av0;
        __stcs(&d0[lane + u * 32], o);
    }
#pragma unroll
    for (int u = 0; u < 4; u++) {
        dot1 += c1[u].x * qv[u].x + c1[u].y * qv[u].y
              + c1[u].z * qv[u].z + c1[u].w * qv[u].w;
        float4 o;
        o.x = fv1 * c1[u].x + av1;
        o.y = fv1 * c1[u].y + av1;
        o.z = fv1 * c1[u].z + av1;
        o.w = fv1 * c1[u].w + av1;
        __stcs(&d1[lane + u * 32], o);
    }
    for (int s = 16; s; s >>= 1) {
        dot0 += __shfl_xor_sync(0xffffffffu, dot0, s);
        dot1 += __shfl_xor_sync(0xffffffffu, dot1, s);
    }
    if (lane == 0) {
        float sumq = g_sumq[b], invd = g_invden[b];
        out[OUT_H + bh0] = g_o[bh0] * (fv0 * dot0 + av0 * sumq) * invd;
        out[OUT_H + bh1] = g_o[bh1] * (fv1 * dot1 + av1 * sumq) * invd;
    }
}

// ---------------------------------------------------------------------------
// Launch. Inputs (metadata order): x, h_prev, C_prev, m_prev, n_prev, W, b
// ---------------------------------------------------------------------------
extern "C" void kernel_launch(void* const* d_in, const int* in_sizes, int n_in,
                              void* d_out, int out_size)
{
    const float* x      = (const float*)d_in[0];
    // d_in[1] = h_prev (unused by reference)
    const float* C_prev = (const float*)d_in[2];
    const float* m_prev = (const float*)d_in[3];
    const float* n_prev = (const float*)d_in[4];
    const float* W      = (const float*)d_in[5];
    const float* bias   = (const float*)d_in[6];
    float* out = (float*)d_out;

    // K1: split-K fp32 GEMM, 4x4 reg tile (384 blocks x 128 threads)
    dim3 ggrid(NG / SBN, BATCH / SBM, 2);
    gemm_splitk_kernel<<<ggrid, 128>>>(x, W);

    // K2: fused split-K sum + bias + gate elementwise + reductions
    gatered_kernel<<<BATCH, 512>>>(m_prev, n_prev, bias, out);

    // K3: C stream (2 rows/warp) + fused Cq + h_t
    stream_C_kernel<<<BATCH * (HDIM / 16), 256>>>(C_prev, out);
}